// round 8
// baseline (speedup 1.0000x reference)
#include <cuda_runtime.h>
#include <cuda_bf16.h>
#include <math.h>
#include <stdint.h>

#define B_SZ 32
#define L_SZ 32768
#define PS_SZ 32
#define T_SZ 1024
#define D_SZ 256
#define NTOK (B_SZ * T_SZ)   // 32768

// ---------------- scratch (no allocs allowed; BSS device globals) ----------------
__device__ float g_xn[B_SZ * L_SZ];                  // normalized series fp32 (loss target)
__device__ __nv_bfloat16 g_xnh[B_SZ * L_SZ];         // normalized series bf16 (embed input)
__device__ __nv_bfloat16 g_hh[NTOK * D_SZ];          // patch embedding bf16
__device__ __nv_bfloat16 g_qkvh[NTOK * 3 * D_SZ];    // qkv bf16
__device__ __nv_bfloat16 g_attnh[NTOK * D_SZ];       // attention out bf16
__device__ __nv_bfloat16 g_Wp[PS_SZ * D_SZ];         // W_proj bf16
__device__ __nv_bfloat16 g_Wq[D_SZ * 3 * D_SZ];      // W_qkv bf16
__device__ __nv_bfloat16 g_Woh[D_SZ * PS_SZ];        // W_out @ W_head, bf16
__device__ float g_boh[PS_SZ];                       // b_out @ W_head + b_head
__device__ float g_partial[4096];                    // per-block loss partials

// ---------------- small PTX helpers ----------------
__device__ __forceinline__ uint32_t smem_u32(const void* p) {
    uint32_t a;
    asm("{ .reg .u64 t; cvta.to.shared.u64 t, %1; cvt.u32.u64 %0, t; }"
        : "=r"(a) : "l"(p));
    return a;
}
__device__ __forceinline__ void ldsm4(uint32_t& r0, uint32_t& r1, uint32_t& r2,
                                      uint32_t& r3, uint32_t addr) {
    asm volatile("ldmatrix.sync.aligned.m8n8.x4.shared.b16 {%0,%1,%2,%3}, [%4];"
                 : "=r"(r0), "=r"(r1), "=r"(r2), "=r"(r3) : "r"(addr));
}
__device__ __forceinline__ void ldsm4t(uint32_t& r0, uint32_t& r1, uint32_t& r2,
                                       uint32_t& r3, uint32_t addr) {
    asm volatile("ldmatrix.sync.aligned.m8n8.x4.trans.shared.b16 {%0,%1,%2,%3}, [%4];"
                 : "=r"(r0), "=r"(r1), "=r"(r2), "=r"(r3) : "r"(addr));
}
__device__ __forceinline__ void mma_bf16(float* c, uint32_t a0, uint32_t a1,
                                         uint32_t a2, uint32_t a3,
                                         uint32_t b0, uint32_t b1) {
    asm volatile(
        "mma.sync.aligned.m16n8k16.row.col.f32.bf16.bf16.f32 "
        "{%0,%1,%2,%3}, {%4,%5,%6,%7}, {%8,%9}, {%0,%1,%2,%3};"
        : "+f"(c[0]), "+f"(c[1]), "+f"(c[2]), "+f"(c[3])
        : "r"(a0), "r"(a1), "r"(a2), "r"(a3), "r"(b0), "r"(b1));
}
__device__ __forceinline__ uint32_t pack_bf16(float lo, float hi) {
    uint32_t d;
    asm("cvt.rn.bf16x2.f32 %0, %1, %2;" : "=r"(d) : "f"(hi), "f"(lo));
    return d;
}
__device__ __forceinline__ void cp16(uint32_t saddr, const void* gaddr) {
    asm volatile("cp.async.cg.shared.global [%0], [%1], 16;"
                 :: "r"(saddr), "l"(gaddr));
}

// ---------------- 0) weight prep: bf16 conversion + W_out@W_head folding -----------
// blocks [0,200): convert W_proj+W_qkv quads; blocks [200,232): fold W_oh/b_oh.
__global__ __launch_bounds__(256) void prep_weights(
        const float* __restrict__ Wp, const float* __restrict__ Wq,
        const float* __restrict__ Wo, const float* __restrict__ Whd,
        const float* __restrict__ bo, const float* __restrict__ bhd) {
    int bx = blockIdx.x;
    if (bx < 200) {
        int q = bx * 256 + threadIdx.x;     // 51200 quads total
        const float* src;
        __nv_bfloat16* dst;
        int idx;
        if (q < PS_SZ * D_SZ / 4) { src = Wp; dst = g_Wp; idx = q * 4; }
        else { src = Wq; dst = g_Wq; idx = (q - PS_SZ * D_SZ / 4) * 4; }
        float4 v = *(const float4*)(src + idx);
        __nv_bfloat16 t[4] = {__float2bfloat16(v.x), __float2bfloat16(v.y),
                              __float2bfloat16(v.z), __float2bfloat16(v.w)};
        *(uint2*)(dst + idx) = *(uint2*)t;
    } else {
        int e = (bx - 200) * 256 + threadIdx.x;   // 8192 outputs
        int i = e >> 5, j = e & 31;
        float acc = 0.f;
        #pragma unroll 8
        for (int k = 0; k < 256; k++)
            acc += Wo[i * 256 + k] * Whd[k * 32 + j];
        g_Woh[e] = __float2bfloat16(acc);
        if (e < 32) {
            float b = 0.f;
            for (int k = 0; k < 256; k++) b += bo[k] * Whd[k * 32 + e];
            g_boh[e] = b + bhd[e];
        }
    }
}

// ---------------- 1) instance norm over full series (ddof=1), vectorized ----------
__global__ __launch_bounds__(1024) void norm_kernel(const float* __restrict__ x) {
    int b = blockIdx.x;
    const float4* xr = (const float4*)(x + (size_t)b * L_SZ);
    float s = 0.f, sq = 0.f;
    for (int i = threadIdx.x; i < L_SZ / 4; i += 1024) {
        float4 v = xr[i];
        s  += v.x + v.y + v.z + v.w;
        sq += v.x * v.x + v.y * v.y + v.z * v.z + v.w * v.w;
    }
    for (int o = 16; o > 0; o >>= 1) {
        s  += __shfl_xor_sync(0xffffffffu, s,  o);
        sq += __shfl_xor_sync(0xffffffffu, sq, o);
    }
    __shared__ float ss[32], ssq[32];
    __shared__ float sm_mean, sm_inv;
    int w = threadIdx.x >> 5;
    if ((threadIdx.x & 31) == 0) { ss[w] = s; ssq[w] = sq; }
    __syncthreads();
    if (threadIdx.x == 0) {
        float S = 0.f, SQ = 0.f;
        #pragma unroll
        for (int i = 0; i < 32; i++) { S += ss[i]; SQ += ssq[i]; }
        float mean = S / (float)L_SZ;
        float var = (SQ - (float)L_SZ * mean * mean) / (float)(L_SZ - 1);
        sm_mean = mean;
        sm_inv = 1.0f / (sqrtf(var) + 1e-5f);
    }
    __syncthreads();
    float mean = sm_mean, inv = sm_inv;
    float4* op = (float4*)(g_xn + (size_t)b * L_SZ);
    uint2* oph = (uint2*)(g_xnh + (size_t)b * L_SZ);
    for (int i = threadIdx.x; i < L_SZ / 4; i += 1024) {
        float4 v = xr[i];
        float4 nv = make_float4((v.x - mean) * inv, (v.y - mean) * inv,
                                (v.z - mean) * inv, (v.w - mean) * inv);
        op[i] = nv;
        uint2 h;
        h.x = pack_bf16(nv.x, nv.y);
        h.y = pack_bf16(nv.z, nv.w);
        oph[i] = h;
    }
}

// ---------------- 2) bf16 GEMM v2: cp.async double-buffered mainloop ----------------
#define AS_STRIDE 40
#define BS_STRIDE 136
#define A_TILE (128 * AS_STRIDE)
#define B_TILE (32 * BS_STRIDE)

__global__ __launch_bounds__(256) void hgemm_bias_bf16(
        const __nv_bfloat16* __restrict__ A, const __nv_bfloat16* __restrict__ Bm,
        const float* __restrict__ bias, __nv_bfloat16* __restrict__ C,
        int M, int N, int K) {
    __shared__ __align__(16) __nv_bfloat16 As[2][A_TILE];
    __shared__ __align__(16) __nv_bfloat16 Bs[2][B_TILE];
    int tid = threadIdx.x, w = tid >> 5, t = tid & 31;
    int bm = blockIdx.y * 128, bn = blockIdx.x * 128;
    int wm = (w & 3) * 32, wn = (w >> 2) * 64;

    uint32_t asBase = smem_u32(As), bsBase = smem_u32(Bs);
    int rowA = (t & 7) + ((t >> 3) & 1) * 8;
    uint32_t aLane = (uint32_t)(((wm + rowA) * AS_STRIDE + ((t >> 4) << 3)) * 2);
    uint32_t bLane = (uint32_t)((rowA * BS_STRIDE + wn + ((t >> 4) << 3)) * 2);

    // cp.async destinations for this thread
    int ar = tid >> 1, ac = (tid & 1) << 4;          // A: 128 rows x 2 chunks(16 elems)
    int br = tid >> 3, bc = (tid & 7) << 4;          // B: 32 rows x 8 chunks
    const __nv_bfloat16* agp = A + (size_t)(bm + ar) * K + ac;
    const __nv_bfloat16* bgp;

    float c[2][8][4];
    #pragma unroll
    for (int mi = 0; mi < 2; mi++)
        #pragma unroll
        for (int nj = 0; nj < 8; nj++)
            #pragma unroll
            for (int e = 0; e < 4; e++) c[mi][nj][e] = 0.f;

    // issue stage 0
    {
        uint32_t ad = asBase + (uint32_t)((ar * AS_STRIDE + ac) * 2);
        cp16(ad, agp);
        cp16(ad + 16, agp + 8);
        bgp = Bm + (size_t)br * N + bn + bc;
        uint32_t bd = bsBase + (uint32_t)((br * BS_STRIDE + bc) * 2);
        cp16(bd, bgp);
        cp16(bd + 16, bgp + 8);
        asm volatile("cp.async.commit_group;");
    }

    int nk = K >> 5;
    for (int kt = 0; kt < nk; kt++) {
        int s = kt & 1;
        if (kt + 1 < nk) {
            int k0 = (kt + 1) << 5;
            uint32_t so = (uint32_t)((s ^ 1) ? (A_TILE * 2) : 0);
            uint32_t ad = asBase + ((s ^ 1) ? (uint32_t)(A_TILE * 2) : 0u) +
                          (uint32_t)((ar * AS_STRIDE + ac) * 2);
            cp16(ad, agp + k0);
            cp16(ad + 16, agp + k0 + 8);
            const __nv_bfloat16* bg = Bm + (size_t)(k0 + br) * N + bn + bc;
            uint32_t bd = bsBase + ((s ^ 1) ? (uint32_t)(B_TILE * 2) : 0u) +
                          (uint32_t)((br * BS_STRIDE + bc) * 2);
            cp16(bd, bg);
            cp16(bd + 16, bg + 8);
            asm volatile("cp.async.commit_group;");
            asm volatile("cp.async.wait_group 1;");
            (void)so;
        } else {
            asm volatile("cp.async.wait_group 0;");
        }
        __syncthreads();

        uint32_t aBase = asBase + (s ? (uint32_t)(A_TILE * 2) : 0u) + aLane;
        uint32_t bBase = bsBase + (s ? (uint32_t)(B_TILE * 2) : 0u) + bLane;
        #pragma unroll
        for (int kf = 0; kf < 2; kf++) {
            uint32_t a0[2], a1[2], a2[2], a3[2];
            #pragma unroll
            for (int mi = 0; mi < 2; mi++)
                ldsm4(a0[mi], a1[mi], a2[mi], a3[mi],
                      aBase + mi * (16 * AS_STRIDE * 2) + kf * 32);
            #pragma unroll
            for (int nf = 0; nf < 4; nf++) {
                uint32_t b0, b1, b2, b3;
                ldsm4t(b0, b1, b2, b3,
                       bBase + kf * (16 * BS_STRIDE * 2) + nf * 32);
                #pragma unroll
                for (int mi = 0; mi < 2; mi++) {
                    mma_bf16(c[mi][2 * nf],     a0[mi], a1[mi], a2[mi], a3[mi], b0, b1);
                    mma_bf16(c[mi][2 * nf + 1], a0[mi], a1[mi], a2[mi], a3[mi], b2, b3);
                }
            }
        }
        __syncthreads();
    }

    #pragma unroll
    for (int nj = 0; nj < 8; nj++) {
        int cb = bn + wn + nj * 8 + (t & 3) * 2;
        float bz0 = bias[cb], bz1 = bias[cb + 1];
        #pragma unroll
        for (int mi = 0; mi < 2; mi++) {
            int r0 = bm + wm + mi * 16 + (t >> 2);
            *(uint32_t*)(C + (size_t)r0 * N + cb) =
                pack_bf16(c[mi][nj][0] + bz0, c[mi][nj][1] + bz1);
            *(uint32_t*)(C + (size_t)(r0 + 8) * N + cb) =
                pack_bf16(c[mi][nj][2] + bz0, c[mi][nj][3] + bz1);
        }
    }
}

// ---------------- 3) causal flash attention v3: paired q-blocks, cp.async ----------
#define FH_STRIDE 264
#define FAM_SMEM ((128 * FH_STRIDE + 4 * 64 * FH_STRIDE) * 2)

__device__ __forceinline__ void issue_kv(uint32_t smemBase,
                                         const __nv_bfloat16* base, int kt, int s,
                                         int tid) {
    const __nv_bfloat16* kptr = base + (size_t)(kt * 64) * 768;
    uint32_t kOff = smemBase + (uint32_t)((128 * FH_STRIDE + s * 2 * 64 * FH_STRIDE) * 2);
    uint32_t vOff = kOff + (uint32_t)(64 * FH_STRIDE * 2);
    #pragma unroll
    for (int p = 0; p < 8; p++) {
        int i = tid + p * 256;
        int row = i >> 5, c8 = (i & 31) << 3;
        uint32_t so = (uint32_t)((row * FH_STRIDE + c8) * 2);
        cp16(kOff + so, kptr + row * 768 + 256 + c8);
        cp16(vOff + so, kptr + row * 768 + 512 + c8);
    }
    asm volatile("cp.async.commit_group;");
}

__global__ __launch_bounds__(256, 1) void flash_mma_kernel(
        const __nv_bfloat16* __restrict__ qkv, __nv_bfloat16* __restrict__ outp) {
    extern __shared__ __nv_bfloat16 smb[];
    uint32_t smemBase = smem_u32(smb);

    int b = blockIdx.y;
    int tid = threadIdx.x;
    int w = tid >> 5, t = tid & 31;
    const __nv_bfloat16* base = qkv + (size_t)b * T_SZ * 768;

    int rowA = (t & 7) + ((t >> 3) & 1) * 8;
    uint32_t aBase = smemBase +
        (uint32_t)(((16 * w + rowA) * FH_STRIDE + ((t >> 4) << 3)) * 2);
    int matB = t >> 3;
    uint32_t bLane =
        (uint32_t)((((t & 7) + (matB >> 1) * 8) * FH_STRIDE + ((matB & 1) << 3)) * 2);
    uint32_t vLane = (uint32_t)((rowA * FH_STRIDE + ((t >> 4) << 3)) * 2);

    #pragma unroll 1
    for (int pass = 0; pass < 2; pass++) {
        int qb = pass ? (int)blockIdx.x : 7 - (int)blockIdx.x;
        const __nv_bfloat16* qbase = base + (size_t)(qb * 128) * 768;

        for (int p = 0; p < 16; p++) {
            int i = tid + p * 256;
            int row = i >> 5, c8 = (i & 31) << 3;
            *(uint4*)&smb[row * FH_STRIDE + c8] =
                *(const uint4*)(qbase + row * 768 + c8);
        }

        float o[32][4];
        #pragma unroll
        for (int n = 0; n < 32; n++)
            #pragma unroll
            for (int e = 0; e < 4; e++) o[n][e] = 0.f;
        float m0 = -1e30f, m1 = -1e30f, l0 = 0.f, l1 = 0.f;

        int nt = 2 * qb + 2;
        issue_kv(smemBase, base, 0, 0, tid);

        for (int kt = 0; kt < nt; kt++) {
            int s = kt & 1;
            if (kt + 1 < nt) {
                issue_kv(smemBase, base, kt + 1, s ^ 1, tid);
                asm volatile("cp.async.wait_group 1;");
            } else {
                asm volatile("cp.async.wait_group 0;");
            }
            __syncthreads();

            bool skip = (64 * kt > 128 * qb + 16 * w + 15);
            if (!skip) {
                uint32_t kOff = smemBase +
                    (uint32_t)((128 * FH_STRIDE + s * 2 * 64 * FH_STRIDE) * 2);
                uint32_t bBase = kOff + bLane;
                uint32_t vBase = kOff + (uint32_t)(64 * FH_STRIDE * 2) + vLane;

                float c[8][4];
                #pragma unroll
                for (int j = 0; j < 8; j++)
                    #pragma unroll
                    for (int e = 0; e < 4; e++) c[j][e] = 0.f;

                #pragma unroll
                for (int kf = 0; kf < 16; kf++) {
                    uint32_t a0, a1, a2, a3;
                    ldsm4(a0, a1, a2, a3, aBase + kf * 32);
                    #pragma unroll
                    for (int nf = 0; nf < 4; nf++) {
                        uint32_t b0, b1, b2, b3;
                        ldsm4(b0, b1, b2, b3,
                              bBase + nf * (16 * FH_STRIDE * 2) + kf * 32);
                        mma_bf16(c[2 * nf],     a0, a1, a2, a3, b0, b1);
                        mma_bf16(c[2 * nf + 1], a0, a1, a2, a3, b2, b3);
                    }
                }

                #pragma unroll
                for (int j = 0; j < 8; j++)
                    #pragma unroll
                    for (int e = 0; e < 4; e++) c[j][e] *= 0.0625f;

                int rowg0 = 128 * qb + 16 * w + (t >> 2);
                int rowg1 = rowg0 + 8;
                if (64 * kt + 63 > 128 * qb + 16 * w) {
                    #pragma unroll
                    for (int j = 0; j < 8; j++) {
                        int colg = 64 * kt + 8 * j + (t & 3) * 2;
                        if (colg     > rowg0) c[j][0] = -1e30f;
                        if (colg + 1 > rowg0) c[j][1] = -1e30f;
                        if (colg     > rowg1) c[j][2] = -1e30f;
                        if (colg + 1 > rowg1) c[j][3] = -1e30f;
                    }
                }

                float mx0 = -1e30f, mx1 = -1e30f;
                #pragma unroll
                for (int j = 0; j < 8; j++) {
                    mx0 = fmaxf(mx0, fmaxf(c[j][0], c[j][1]));
                    mx1 = fmaxf(mx1, fmaxf(c[j][2], c[j][3]));
                }
                mx0 = fmaxf(mx0, __shfl_xor_sync(0xffffffffu, mx0, 1));
                mx0 = fmaxf(mx0, __shfl_xor_sync(0xffffffffu, mx0, 2));
                mx1 = fmaxf(mx1, __shfl_xor_sync(0xffffffffu, mx1, 1));
                mx1 = fmaxf(mx1, __shfl_xor_sync(0xffffffffu, mx1, 2));
                float mn0 = fmaxf(m0, mx0), mn1 = fmaxf(m1, mx1);
                float al0 = __expf(m0 - mn0), al1 = __expf(m1 - mn1);
                m0 = mn0; m1 = mn1;
                float s0 = 0.f, s1 = 0.f;
                #pragma unroll
                for (int j = 0; j < 8; j++) {
                    c[j][0] = __expf(c[j][0] - mn0);
                    c[j][1] = __expf(c[j][1] - mn0);
                    c[j][2] = __expf(c[j][2] - mn1);
                    c[j][3] = __expf(c[j][3] - mn1);
                    s0 += c[j][0] + c[j][1];
                    s1 += c[j][2] + c[j][3];
                }
                s0 += __shfl_xor_sync(0xffffffffu, s0, 1);
                s0 += __shfl_xor_sync(0xffffffffu, s0, 2);
                s1 += __shfl_xor_sync(0xffffffffu, s1, 1);
                s1 += __shfl_xor_sync(0xffffffffu, s1, 2);
                l0 = l0 * al0 + s0;
                l1 = l1 * al1 + s1;
                #pragma unroll
                for (int n = 0; n < 32; n++) {
                    o[n][0] *= al0; o[n][1] *= al0;
                    o[n][2] *= al1; o[n][3] *= al1;
                }

                uint32_t p[4][4];
                #pragma unroll
                for (int f = 0; f < 4; f++) {
                    p[f][0] = pack_bf16(c[2 * f][0],     c[2 * f][1]);
                    p[f][1] = pack_bf16(c[2 * f][2],     c[2 * f][3]);
                    p[f][2] = pack_bf16(c[2 * f + 1][0], c[2 * f + 1][1]);
                    p[f][3] = pack_bf16(c[2 * f + 1][2], c[2 * f + 1][3]);
                }

                #pragma unroll
                for (int f = 0; f < 4; f++) {
                    #pragma unroll
                    for (int nf = 0; nf < 16; nf++) {
                        uint32_t b0, b1, b2, b3;
                        ldsm4t(b0, b1, b2, b3,
                               vBase + f * (16 * FH_STRIDE * 2) + nf * 32);
                        mma_bf16(o[2 * nf],     p[f][0], p[f][1], p[f][2], p[f][3],
                                 b0, b1);
                        mma_bf16(o[2 * nf + 1], p[f][0], p[f][1], p[f][2], p[f][3],
                                 b2, b3);
                    }
                }
            }
            __syncthreads();
        }

        float inv0 = 1.0f / l0, inv1 = 1.0f / l1;
        int gr0 = qb * 128 + 16 * w + (t >> 2);
        __nv_bfloat16* op0 = outp + ((size_t)b * T_SZ + gr0) * 256;
        __nv_bfloat16* op1 = op0 + 8 * 256;
        #pragma unroll
        for (int n = 0; n < 32; n++) {
            int col = 8 * n + (t & 3) * 2;
            *(uint32_t*)(op0 + col) = pack_bf16(o[n][0] * inv0, o[n][1] * inv0);
            *(uint32_t*)(op1 + col) = pack_bf16(o[n][2] * inv1, o[n][3] * inv1);
        }
    }
}

// ---------------- 4) head GEMM (tensor cores, W_out folded) + shifted-target MSE ----
#define HD_XS 264
#define HD_WS 40
#define HEAD_SMEM ((128 * HD_XS + 256 * HD_WS) * 2)

__global__ __launch_bounds__(128) void head_mma_loss(
        const __nv_bfloat16* __restrict__ X, const __nv_bfloat16* __restrict__ Wh,
        const float* __restrict__ bh) {
    extern __shared__ __nv_bfloat16 hsm[];
    __nv_bfloat16* Xs = hsm;                 // [128][264]
    __nv_bfloat16* Ws = hsm + 128 * HD_XS;   // [256][40]
    int tid = threadIdx.x, w = tid >> 5, t = tid & 31;
    int tok0 = blockIdx.x * 128;

    #pragma unroll
    for (int p = 0; p < 32; p++) {
        int i = tid + p * 128;
        int row = i >> 5, c8 = (i & 31) << 3;
        *(uint4*)&Xs[row * HD_XS + c8] =
            *(const uint4*)(X + (size_t)(tok0 + row) * 256 + c8);
    }
    #pragma unroll
    for (int p = 0; p < 8; p++) {
        int i = tid + p * 128;
        int row = i >> 2, c8 = (i & 3) << 3;
        *(uint4*)&Ws[row * HD_WS + c8] = *(const uint4*)(Wh + row * 32 + c8);
    }
    __syncthreads();

    int rowA = (t & 7) + ((t >> 3) & 1) * 8;
    uint32_t aBase = smem_u32(Xs) +
        (uint32_t)(((32 * w + rowA) * HD_XS + ((t >> 4) << 3)) * 2);
    uint32_t bBase = smem_u32(Ws) +
        (uint32_t)((rowA * HD_WS + ((t >> 4) << 3)) * 2);

    float c[2][4][4];
    #pragma unroll
    for (int mi = 0; mi < 2; mi++)
        #pragma unroll
        for (int nj = 0; nj < 4; nj++)
            #pragma unroll
            for (int e = 0; e < 4; e++) c[mi][nj][e] = 0.f;

    #pragma unroll
    for (int kf = 0; kf < 16; kf++) {
        uint32_t a0[2], a1[2], a2[2], a3[2];
        #pragma unroll
        for (int mi = 0; mi < 2; mi++)
            ldsm4(a0[mi], a1[mi], a2[mi], a3[mi],
                  aBase + mi * (16 * HD_XS * 2) + kf * 32);
        #pragma unroll
        for (int nn = 0; nn < 2; nn++) {
            uint32_t b0, b1, b2, b3;
            ldsm4t(b0, b1, b2, b3, bBase + kf * (16 * HD_WS * 2) + nn * 32);
            #pragma unroll
            for (int mi = 0; mi < 2; mi++) {
                mma_bf16(c[mi][2 * nn],     a0[mi], a1[mi], a2[mi], a3[mi], b0, b1);
                mma_bf16(c[mi][2 * nn + 1], a0[mi], a1[mi], a2[mi], a3[mi], b2, b3);
            }
        }
    }

    float d2 = 0.f;
    #pragma unroll
    for (int nj = 0; nj < 4; nj++) {
        int col = nj * 8 + (t & 3) * 2;
        float bz0 = __ldg(&bh[col]), bz1 = __ldg(&bh[col + 1]);
        #pragma unroll
        for (int mi = 0; mi < 2; mi++) {
            int r0 = tok0 + w * 32 + mi * 16 + (t >> 2);
            #pragma unroll
            for (int half = 0; half < 2; half++) {
                int rg = r0 + half * 8;
                int tt = rg & 1023, bb = rg >> 10;
                if (tt < T_SZ - 1) {
                    const float* tp = g_xn + (size_t)bb * L_SZ + (tt + 1) * PS_SZ + col;
                    float p0 = c[mi][nj][2 * half]     + bz0;
                    float p1 = c[mi][nj][2 * half + 1] + bz1;
                    float e0 = p0 - tp[0], e1 = p1 - tp[1];
                    d2 += e0 * e0 + e1 * e1;
                }
            }
        }
    }
    #pragma unroll
    for (int o = 16; o > 0; o >>= 1) d2 += __shfl_xor_sync(0xffffffffu, d2, o);
    __shared__ float red[4];
    if (t == 0) red[w] = d2;
    __syncthreads();
    if (tid == 0)
        g_partial[blockIdx.x] = red[0] + red[1] + red[2] + red[3];
}

__global__ __launch_bounds__(256) void finalize_kernel(float* __restrict__ out) {
    __shared__ double red[256];
    double s = (threadIdx.x < 256) ? (double)g_partial[threadIdx.x] : 0.0;
    red[threadIdx.x] = s;
    __syncthreads();
    for (int st = 128; st > 0; st >>= 1) {
        if (threadIdx.x < st) red[threadIdx.x] += red[threadIdx.x + st];
        __syncthreads();
    }
    if (threadIdx.x == 0)
        out[0] = (float)(red[0] / (double)((size_t)B_SZ * (T_SZ - 1) * PS_SZ));
}

// ---------------- launch ----------------
extern "C" void kernel_launch(void* const* d_in, const int* in_sizes, int n_in,
                              void* d_out, int out_size) {
    const float* x      = (const float*)d_in[0];
    const float* W_proj = (const float*)d_in[1];
    const float* b_proj = (const float*)d_in[2];
    const float* W_qkv  = (const float*)d_in[3];
    const float* b_qkv  = (const float*)d_in[4];
    const float* W_out  = (const float*)d_in[5];
    const float* b_out  = (const float*)d_in[6];
    const float* W_head = (const float*)d_in[7];
    const float* b_head = (const float*)d_in[8];

    __nv_bfloat16 *xnh, *hh, *qkvh, *attnh, *Wp, *Wq, *Woh;
    float* boh;
    cudaGetSymbolAddress((void**)&xnh,   g_xnh);
    cudaGetSymbolAddress((void**)&hh,    g_hh);
    cudaGetSymbolAddress((void**)&qkvh,  g_qkvh);
    cudaGetSymbolAddress((void**)&attnh, g_attnh);
    cudaGetSymbolAddress((void**)&Wp,    g_Wp);
    cudaGetSymbolAddress((void**)&Wq,    g_Wq);
    cudaGetSymbolAddress((void**)&Woh,   g_Woh);
    cudaGetSymbolAddress((void**)&boh,   g_boh);

    cudaFuncSetAttribute(flash_mma_kernel,
                         cudaFuncAttributeMaxDynamicSharedMemorySize, FAM_SMEM);
    cudaFuncSetAttribute(head_mma_loss,
                         cudaFuncAttributeMaxDynamicSharedMemorySize, HEAD_SMEM);

    // 0) weight prep (single launch: conversions + folding)
    prep_weights<<<232, 256>>>(W_proj, W_qkv, W_out, W_head, b_out, b_head);
    // 1) instance norm (fp32 target + bf16 embed input)
    norm_kernel<<<B_SZ, 1024>>>(x);
    // 2) patch embedding
    hgemm_bias_bf16<<<dim3(2, 256), 256>>>(xnh, Wp, b_proj, hh, NTOK, D_SZ, PS_SZ);
    // 3) qkv
    hgemm_bias_bf16<<<dim3(6, 256), 256>>>(hh, Wq, b_qkv, qkvh, NTOK, 3 * D_SZ, D_SZ);
    // 4) causal flash attention v3 (paired q-blocks, single balanced wave)
    flash_mma_kernel<<<dim3(4, B_SZ), 256, FAM_SMEM>>>(qkvh, attnh);
    // 5) head GEMM (W_out folded in) + shifted-MSE, 6) deterministic finalize
    head_mma_loss<<<NTOK / 128, 128, HEAD_SMEM>>>(attnh, Woh, boh);
    finalize_kernel<<<1, 256>>>((float*)d_out);
}